// round 14
// baseline (speedup 1.0000x reference)
#include <cuda_runtime.h>
#include <cuda_fp16.h>
#include <cstdint>

#define S 2048
#define HID 4096
#define NH 32
#define NKV 8
#define HD 128
#define QKVN 6144            // 4096 (q) + 1024 (k) + 1024 (v)

// ---------------- scratch (no allocation allowed) ----------------
__device__ float  g_qkv[(size_t)S * QKVN];
__device__ __half g_att_h[(size_t)S * NH * HD];
__device__ __half g_hs_h[(size_t)S * HID];
__device__ __half g_wq_h[(size_t)NH * HD * HID];
__device__ __half g_wk_h[(size_t)NKV * HD * HID];
__device__ __half g_wv_h[(size_t)NKV * HD * HID];
__device__ __half g_wo_h[(size_t)HID * NH * HD];
// flash pre-split hi/lo planes (k16-interleaved, flash-private layout)
__device__ __half g_q_s[(size_t)S * NH * 256];     // [s][h][2][128]
__device__ __half g_k_s[(size_t)S * NKV * 256];    // [s][kvh][2][128]
__device__ __half g_vt[(size_t)NKV * 2 * HD * S];  // [kvh][2][d][s-interleaved]

// ---------------- helpers ----------------
__device__ __forceinline__ void mma16816(float* d, uint32_t a0, uint32_t a1,
                                         uint32_t a2, uint32_t a3,
                                         uint32_t b0, uint32_t b1) {
    asm volatile(
        "mma.sync.aligned.m16n8k16.row.col.f32.f16.f16.f32 "
        "{%0,%1,%2,%3}, {%4,%5,%6,%7}, {%8,%9}, {%0,%1,%2,%3};"
        : "+f"(d[0]), "+f"(d[1]), "+f"(d[2]), "+f"(d[3])
        : "r"(a0), "r"(a1), "r"(a2), "r"(a3), "r"(b0), "r"(b1));
}

__device__ __forceinline__ void ldsm_x4(uint32_t& r0, uint32_t& r1,
                                        uint32_t& r2, uint32_t& r3, uint32_t addr) {
    asm volatile("ldmatrix.sync.aligned.m8n8.x4.shared.b16 {%0,%1,%2,%3}, [%4];"
                 : "=r"(r0), "=r"(r1), "=r"(r2), "=r"(r3) : "r"(addr));
}

__device__ __forceinline__ void split2(float x, float y, uint32_t& hi, uint32_t& lo) {
    __half2 h = __floats2half2_rn(x, y);
    float2 r = __half22float2(h);
    __half2 l = __floats2half2_rn(x - r.x, y - r.y);
    hi = *(uint32_t*)&h;
    lo = *(uint32_t*)&l;
}

__device__ __forceinline__ uint32_t smem_u32(const void* p) {
    uint32_t a;
    asm("{ .reg .u64 t; cvta.to.shared.u64 t, %1; cvt.u32.u64 %0, t; }" : "=r"(a) : "l"(p));
    return a;
}

__device__ __forceinline__ void cp_async16(uint32_t saddr, const void* gaddr) {
    asm volatile("cp.async.cg.shared.global [%0], [%1], 16;"
                 :: "r"(saddr), "l"(gaddr) : "memory");
}
#define CP_COMMIT() asm volatile("cp.async.commit_group;" ::: "memory")
#define CP_WAIT1()  asm volatile("cp.async.wait_group 1;" ::: "memory")
#define CP_WAIT0()  asm volatile("cp.async.wait_group 0;" ::: "memory")

__device__ __forceinline__ void lds64(uint32_t& x, uint32_t& y, uint32_t addr) {
    asm volatile("ld.shared.v2.b32 {%0,%1}, [%2];" : "=r"(x), "=r"(y) : "r"(addr));
}

// ---------------- plain fp16 conversion ----------------
__global__ void round_fp16_kernel(const float* __restrict__ in,
                                  __half* __restrict__ out, int n8) {
    int i = blockIdx.x * blockDim.x + threadIdx.x;
    if (i >= n8) return;
    float4 a = ((const float4*)in)[2 * i];
    float4 b = ((const float4*)in)[2 * i + 1];
    __half2 h0 = __floats2half2_rn(a.x, a.y);
    __half2 h1 = __floats2half2_rn(a.z, a.w);
    __half2 h2 = __floats2half2_rn(b.x, b.y);
    __half2 h3 = __floats2half2_rn(b.z, b.w);
    uint4 o;
    o.x = *(uint32_t*)&h0; o.y = *(uint32_t*)&h1;
    o.z = *(uint32_t*)&h2; o.w = *(uint32_t*)&h3;
    ((uint4*)out)[i] = o;
}

__global__ void round2_fp16_kernel(const float* __restrict__ inA, __half* __restrict__ outA, int n8A,
                                   const float* __restrict__ inB, __half* __restrict__ outB, int n8B) {
    int i = blockIdx.x * blockDim.x + threadIdx.x;
    const float4* src;
    uint4* dst;
    int j;
    if (i < n8A) { src = (const float4*)inA; dst = (uint4*)outA; j = i; }
    else { j = i - n8A; if (j >= n8B) return; src = (const float4*)inB; dst = (uint4*)outB; }
    float4 a = src[2 * j], b = src[2 * j + 1];
    __half2 h0 = __floats2half2_rn(a.x, a.y);
    __half2 h1 = __floats2half2_rn(a.z, a.w);
    __half2 h2 = __floats2half2_rn(b.x, b.y);
    __half2 h3 = __floats2half2_rn(b.z, b.w);
    uint4 o;
    o.x = *(uint32_t*)&h0; o.y = *(uint32_t*)&h1;
    o.z = *(uint32_t*)&h2; o.w = *(uint32_t*)&h3;
    dst[j] = o;
}

// ==================================================================
// fp16 GEMM (R13 verbatim): CTA 128x128, BK=64, warp 64x32,
// ldmatrix frags, 2-stage cp.async, 2 CTAs/SM.
// ==================================================================
#define BM 128
#define BN 128
#define BK 64
#define ROWB 144
#define TILEB (BM * ROWB)                 // 18432
#define STAGEB (2 * TILEB)                // 36864
#define GEMM_SMEM (2 * STAGEB)            // 73728 B

__global__ __launch_bounds__(256, 2) void gemm_tc(
        const __half* __restrict__ A,
        const __half* __restrict__ B0, const __half* __restrict__ B1,
        const __half* __restrict__ B2, int nb0, int nb1,
        float* __restrict__ C, int M, int N, int K) {
    extern __shared__ __align__(16) char smem[];
    const uint32_t sb = smem_u32(smem);

    const int tid = threadIdx.x;
    const int wid = tid >> 5;
    const int lane = tid & 31;
    const int wm = wid & 1;
    const int wn = wid >> 1;
    const int lr = lane >> 2;
    const int lc = lane & 3;

    const size_t row0 = (size_t)blockIdx.y * BM;
    const int col0 = blockIdx.x * BN;

    const __half* B;
    int bo;
    if (col0 < nb0)      { B = B0; bo = col0; }
    else if (col0 < nb1) { B = B1; bo = col0 - nb0; }
    else                 { B = B2; bo = col0 - nb1; }

    const __half* gA[4];
    const __half* gB[4];
    uint32_t sOff[4];
#pragma unroll
    for (int i = 0; i < 4; i++) {
        int cid = tid + 256 * i;
        int r = cid >> 3, c = cid & 7;
        gA[i] = A + (row0 + r) * (size_t)K + c * 8;
        gB[i] = B + (size_t)(bo + r) * K + c * 8;
        sOff[i] = (uint32_t)(r * ROWB + c * 16);
    }

    uint32_t relA[4];
#pragma unroll
    for (int mt = 0; mt < 4; mt++)
        relA[mt] = (uint32_t)((wm * 64 + mt * 16 + (lane & 15)) * ROWB + (lane >> 4) * 16);
    uint32_t relB[2];
#pragma unroll
    for (int p = 0; p < 2; p++)
        relB[p] = (uint32_t)((wn * 32 + (2 * p + (lane >> 4)) * 8 + (lane & 7)) * ROWB +
                             ((lane >> 3) & 1) * 16);

    float acc[4][4][4];
#pragma unroll
    for (int mt = 0; mt < 4; mt++)
#pragma unroll
        for (int nt = 0; nt < 4; nt++)
#pragma unroll
            for (int e = 0; e < 4; e++) acc[mt][nt][e] = 0.f;

    const int NKc = K / BK;

#pragma unroll
    for (int st = 0; st < 2; st++) {
        uint32_t base = sb + st * STAGEB;
#pragma unroll
        for (int i = 0; i < 4; i++) {
            cp_async16(base + sOff[i], gA[i] + st * BK);
            cp_async16(base + TILEB + sOff[i], gB[i] + st * BK);
        }
        CP_COMMIT();
    }

    for (int kc = 0; kc < NKc; kc++) {
        CP_WAIT1();
        __syncthreads();

        const uint32_t Abase = sb + (kc & 1) * STAGEB;
        const uint32_t Bbase = Abase + TILEB;

#pragma unroll
        for (int g = 0; g < 4; g++) {
            const uint32_t go = (uint32_t)(g * 32);
            uint32_t af[4][4], bf[4][2];
#pragma unroll
            for (int mt = 0; mt < 4; mt++)
                ldsm_x4(af[mt][0], af[mt][1], af[mt][2], af[mt][3],
                        Abase + relA[mt] + go);
#pragma unroll
            for (int p = 0; p < 2; p++)
                ldsm_x4(bf[2 * p][0], bf[2 * p][1], bf[2 * p + 1][0], bf[2 * p + 1][1],
                        Bbase + relB[p] + go);
#pragma unroll
            for (int mt = 0; mt < 4; mt++)
#pragma unroll
                for (int nt = 0; nt < 4; nt++)
                    mma16816(acc[mt][nt], af[mt][0], af[mt][1], af[mt][2], af[mt][3],
                             bf[nt][0], bf[nt][1]);
        }
        __syncthreads();

        if (kc + 2 < NKc) {
            uint32_t base = sb + (kc & 1) * STAGEB;
            const int koff = (kc + 2) * BK;
#pragma unroll
            for (int i = 0; i < 4; i++) {
                cp_async16(base + sOff[i], gA[i] + koff);
                cp_async16(base + TILEB + sOff[i], gB[i] + koff);
            }
        }
        CP_COMMIT();
    }

#pragma unroll
    for (int mt = 0; mt < 4; mt++) {
        size_t rg = row0 + wm * 64 + mt * 16 + lr;
#pragma unroll
        for (int nt = 0; nt < 4; nt++) {
            size_t cg = (size_t)col0 + wn * 32 + nt * 8 + lc * 2;
            *(float2*)(C + rg * N + cg) = make_float2(acc[mt][nt][0], acc[mt][nt][1]);
            *(float2*)(C + (rg + 8) * N + cg) = make_float2(acc[mt][nt][2], acc[mt][nt][3]);
        }
    }
}

// ==================================================================
// RoPE + fp16 hi/lo split (k16-interleaved, flash-private), warp per row.
// ==================================================================
__global__ void rope_split_kernel(const float* __restrict__ src,
                                  const float* __restrict__ cosp,
                                  const float* __restrict__ sinp,
                                  __half* __restrict__ dst,
                                  int nh, float scale) {
    int wpb = blockDim.x >> 5;
    int idx = blockIdx.x * wpb + (threadIdx.x >> 5);
    int lane = threadIdx.x & 31;
    int s = idx / nh, h = idx - s * nh;
    int d0 = 4 * lane;

    const float* row = src + (size_t)s * QKVN + h * HD;
    float4 x = *(const float4*)(row + d0);
    float4 c = *(const float4*)(cosp + s * HD + d0);
    float4 sn = *(const float4*)(sinp + s * HD + d0);
    float xs[4] = {x.x, x.y, x.z, x.w};
    float cs[4] = {c.x, c.y, c.z, c.w};
    float ss[4] = {sn.x, sn.y, sn.z, sn.w};
    float sign = (lane < 16) ? -1.f : 1.f;
    float out[4];
#pragma unroll
    for (int j = 0; j < 4; j++) {
        float p = __shfl_xor_sync(0xffffffffu, xs[j], 16);
        out[j] = (xs[j] * cs[j] + sign * p * ss[j]) * scale;
    }

    int g = lane >> 2;
    int e = 4 * (lane & 3);
    int s0 = (e < 8) ? e : e - 7;
    int s1 = (e + 2 < 8) ? e + 2 : e - 5;

    __half2 h0 = __floats2half2_rn(out[0], out[1]);
    __half2 h1 = __floats2half2_rn(out[2], out[3]);
    float2 r0 = __half22float2(h0), r1 = __half22float2(h1);
    __half2 l0 = __floats2half2_rn(out[0] - r0.x, out[1] - r0.y);
    __half2 l1 = __floats2half2_rn(out[2] - r1.x, out[3] - r1.y);

    __half2* dh = (__half2*)dst;
    size_t base = (size_t)(s * nh + h) * 128;
    dh[base + g * 8 + s0] = h0;
    dh[base + g * 8 + s1] = h1;
    dh[base + 64 + g * 8 + s0] = l0;
    dh[base + 64 + g * 8 + s1] = l1;
}

// ==================================================================
// V transpose + split (flash-private layout).
// ==================================================================
__global__ __launch_bounds__(256) void convert_v_kernel(const float* __restrict__ qkv,
                                                        __half* __restrict__ vt) {
    __shared__ float vsm[64][132];
    int s0 = blockIdx.x * 64;
    int kvh = blockIdx.y;
    int tid = threadIdx.x;

    for (int i = tid; i < 64 * 32; i += 256) {
        int r = i >> 5, c4 = (i & 31) * 4;
        float4 v = *(const float4*)(qkv + (size_t)(s0 + r) * QKVN + 5120 + kvh * HD + c4);
        vsm[r][c4] = v.x; vsm[r][c4 + 1] = v.y; vsm[r][c4 + 2] = v.z; vsm[r][c4 + 3] = v.w;
    }
    __syncthreads();

    int d = tid >> 1, hp = tid & 1;
    float v[32];
#pragma unroll
    for (int j = 0; j < 32; j++) v[j] = vsm[32 * hp + j][d];

#pragma unroll
    for (int g2 = 0; g2 < 2; g2++) {
        __half2 hi[8], lo[8];
#pragma unroll
        for (int slot = 0; slot < 8; slot++) {
            int e = (slot & 1) ? slot + 7 : slot;
            float x = v[g2 * 16 + e], y = v[g2 * 16 + e + 1];
            __half2 hh = __floats2half2_rn(x, y);
            float2 r = __half22float2(hh);
            hi[slot] = hh;
            lo[slot] = __floats2half2_rn(x - r.x, y - r.y);
        }
        int kbase = s0 + (2 * hp + g2) * 16;
        __half2* dhi = (__half2*)vt + ((((size_t)kvh * 2 + 0) * HD + d) * S + kbase) / 2;
        __half2* dlo = (__half2*)vt + ((((size_t)kvh * 2 + 1) * HD + d) * S + kbase) / 2;
#pragma unroll
        for (int slot = 0; slot < 8; slot++) { dhi[slot] = hi[slot]; dlo[slot] = lo[slot]; }
    }
}

// ==================================================================
// Flash attention v2: FQ=128 (8 warps, 256 threads), 2 CTAs/SM.
// Q/K stride 272B (68w ≡ 4 mod 32, near-conflict-free), V 160B.
// PV A-frags from QK^T score registers. K/V tile traffic HALVED
// vs FQ=64 (each tile serves 128 q-rows).
// ==================================================================
#define FQ 128
#define FK 64
#define QKROWB 272
#define VROWB 160
#define Q_PLANE (128 * QKROWB)             // 34816
#define KV_OFF (2 * Q_PLANE)               // 69632
#define KV_BYTES 40960                     // max(K 2*64*272=34816, V 2*128*160=40960)
#define FLASH_SMEM (KV_OFF + KV_BYTES)     // 110592 B -> 2 CTAs/SM

__global__ __launch_bounds__(256, 2) void flash_tc(const __half* __restrict__ Qsg,
                                                   const __half* __restrict__ Ksg,
                                                   const __half* __restrict__ VTg,
                                                   __half* __restrict__ Oh) {
    extern __shared__ __align__(16) char fsm[];
    const uint32_t qhi_b = smem_u32(fsm);
    const uint32_t qlo_b = qhi_b + Q_PLANE;
    const uint32_t kv_b  = qhi_b + KV_OFF;
    const uint32_t klo_b = kv_b + 64 * QKROWB;     // K lo plane
    const uint32_t vlo_b = kv_b + 128 * VROWB;     // V lo plane

    const int h = blockIdx.y;
    const int kvh = h >> 2;
    const int qi = gridDim.x - 1 - blockIdx.x;     // longest first
    const int q0 = qi * FQ;
    const int tid = threadIdx.x;
    const int wid = tid >> 5;
    const int lane = tid & 31;
    const int lr = lane >> 2;
    const int lc = lane & 3;

    // Q tile load: 128 rows x 32 chunks = 4096 chunks / 256 thr = 16 each
#pragma unroll
    for (int ii = 0; ii < 16; ii++) {
        int i = tid + 256 * ii;
        int r = i >> 5, c = i & 31;
        int plane = c >> 4, j = c & 15;
        cp_async16((plane ? qlo_b : qhi_b) + (uint32_t)(r * QKROWB + j * 16),
                   Qsg + ((size_t)(q0 + r) * NH + h) * 256 + plane * 128 + j * 8);
    }
    CP_COMMIT();

    float o[16][4];
#pragma unroll
    for (int nt = 0; nt < 16; nt++)
#pragma unroll
        for (int e = 0; e < 4; e++) o[nt][e] = 0.f;
    float m0 = -1e30f, m1 = -1e30f, l0v = 0.f, l1v = 0.f;

    const int nkt = 2 * (qi + 1);
    for (int kt = 0; kt < nkt; kt++) {
        const int k0 = kt * FK;

        // K tile: 64 rows x 32 chunks = 2048 / 256 = 8 each
#pragma unroll
        for (int ii = 0; ii < 8; ii++) {
            int i = tid + 256 * ii;
            int r = i >> 5, c = i & 31;
            int plane = c >> 4, j = c & 15;
            cp_async16((plane ? klo_b : kv_b) + (uint32_t)(r * QKROWB + j * 16),
                       Ksg + ((size_t)(k0 + r) * NKV + kvh) * 256 + plane * 128 + j * 8);
        }
        CP_COMMIT();
        CP_WAIT0();
        __syncthreads();

        // ---- QK^T ----
        float sa[8][4];
#pragma unroll
        for (int nt = 0; nt < 8; nt++)
#pragma unroll
            for (int e = 0; e < 4; e++) sa[nt][e] = 0.f;

#pragma unroll 2
        for (int ks = 0; ks < 8; ks++) {
            const uint32_t go = (uint32_t)(ks * 32 + lc * 8);
            uint32_t ah[4], al[4];
            {
                uint32_t r = (uint32_t)((wid * 16 + lr) * QKROWB) + go;
                lds64(ah[0], ah[2], qhi_b + r);
                lds64(ah[1], ah[3], qhi_b + r + 8 * QKROWB);
                lds64(al[0], al[2], qlo_b + r);
                lds64(al[1], al[3], qlo_b + r + 8 * QKROWB);
            }
#pragma unroll
            for (int nt = 0; nt < 8; nt++) {
                uint32_t r = (uint32_t)((nt * 8 + lr) * QKROWB) + go;
                uint32_t bh0, bh1, bl0, bl1;
                lds64(bh0, bh1, kv_b + r);
                lds64(bl0, bl1, klo_b + r);
                mma16816(sa[nt], ah[0], ah[1], ah[2], ah[3], bh0, bh1);
                mma16816(sa[nt], ah[0], ah[1], ah[2], ah[3], bl0, bl1);
                mma16816(sa[nt], al[0], al[1], al[2], al[3], bh0, bh1);
            }
        }
        __syncthreads();   // done reading K

        // V^T tile into same buffer (overlaps softmax): 2048 / 256 = 8 each
#pragma unroll
        for (int ii = 0; ii < 8; ii++) {
            int i = tid + 256 * ii;
            int plane = i >> 10;
            int rem = i & 1023;
            int d = rem >> 3, j = rem & 7;
            cp_async16((plane ? vlo_b : kv_b) + (uint32_t)(d * VROWB + j * 16),
                       VTg + (((size_t)kvh * 2 + plane) * HD + d) * S + k0 + j * 8);
        }
        CP_COMMIT();

        // causal mask (only tiles intersecting the diagonal)
        if (kt >= 2 * qi) {
            int r0 = q0 + wid * 16 + lr;
#pragma unroll
            for (int nt = 0; nt < 8; nt++) {
                int c = k0 + nt * 8 + lc * 2;
                if (c > r0)         sa[nt][0] = -1e30f;
                if (c + 1 > r0)     sa[nt][1] = -1e30f;
                if (c > r0 + 8)     sa[nt][2] = -1e30f;
                if (c + 1 > r0 + 8) sa[nt][3] = -1e30f;
            }
        }

        float rx0 = -1e30f, rx1 = -1e30f;
#pragma unroll
        for (int nt = 0; nt < 8; nt++) {
            rx0 = fmaxf(rx0, fmaxf(sa[nt][0], sa[nt][1]));
            rx1 = fmaxf(rx1, fmaxf(sa[nt][2], sa[nt][3]));
        }
        rx0 = fmaxf(rx0, __shfl_xor_sync(0xffffffffu, rx0, 1));
        rx0 = fmaxf(rx0, __shfl_xor_sync(0xffffffffu, rx0, 2));
        rx1 = fmaxf(rx1, __shfl_xor_sync(0xffffffffu, rx1, 1));
        rx1 = fmaxf(rx1, __shfl_xor_sync(0xffffffffu, rx1, 2));

        float mn0 = fmaxf(m0, rx0), mn1 = fmaxf(m1, rx1);
        float a0 = __expf(m0 - mn0), a1 = __expf(m1 - mn1);
        m0 = mn0; m1 = mn1;

        float rs0 = 0.f, rs1 = 0.f;
#pragma unroll
        for (int nt = 0; nt < 8; nt++) {
            sa[nt][0] = __expf(sa[nt][0] - mn0);
            sa[nt][1] = __expf(sa[nt][1] - mn0);
            sa[nt][2] = __expf(sa[nt][2] - mn1);
            sa[nt][3] = __expf(sa[nt][3] - mn1);
            rs0 += sa[nt][0] + sa[nt][1];
            rs1 += sa[nt][2] + sa[nt][3];
        }
        rs0 += __shfl_xor_sync(0xffffffffu, rs0, 1);
        rs0 += __shfl_xor_sync(0xffffffffu, rs0, 2);
        rs1 += __shfl_xor_sync(0xffffffffu, rs1, 1);
        rs1 += __shfl_xor_sync(0xffffffffu, rs1, 2);
        l0v = l0v * a0 + rs0;
        l1v = l1v * a1 + rs1;

#pragma unroll
        for (int nt = 0; nt < 16; nt++) {
            o[nt][0] *= a0; o[nt][1] *= a0;
            o[nt][2] *= a1; o[nt][3] *= a1;
        }

        CP_WAIT0();        // V^T landed
        __syncthreads();

        // ---- PV: A-frags straight from sa registers ----
#pragma unroll
        for (int g = 0; g < 4; g++) {
            uint32_t ah[4], al[4];
            split2(sa[2 * g][0], sa[2 * g][1], ah[0], al[0]);
            split2(sa[2 * g][2], sa[2 * g][3], ah[1], al[1]);
            split2(sa[2 * g + 1][0], sa[2 * g + 1][1], ah[2], al[2]);
            split2(sa[2 * g + 1][2], sa[2 * g + 1][3], ah[3], al[3]);
            const uint32_t go = (uint32_t)(g * 32 + lc * 8);
#pragma unroll
            for (int nt = 0; nt < 16; nt++) {
                uint32_t r = (uint32_t)((nt * 8 + lr) * VROWB) + go;
                uint32_t bh0, bh1, bl0, bl1;
                lds64(bh0, bh1, kv_b + r);
                lds64(bl0, bl1, vlo_b + r);
                mma16816(o[nt], ah[0], ah[1], ah[2], ah[3], bh0, bh1);
                mma16816(o[nt], ah[0], ah[1], ah[2], ah[3], bl0, bl1);
                mma16816(o[nt], al[0], al[1], al[2], al[3], bh0, bh1);
            }
        }
        __syncthreads();   // done reading V before next K load
    }

    // epilogue: plain fp16 att rows
    float inv0 = 1.0f / l0v, inv1 = 1.0f / l1v;
    size_t r0 = q0 + wid * 16 + lr;
#pragma unroll
    for (int nt = 0; nt < 16; nt++) {
        size_t c = h * HD + nt * 8 + lc * 2;
        __half2 v0 = __floats2half2_rn(o[nt][0] * inv0, o[nt][1] * inv0);
        __half2 v1 = __floats2half2_rn(o[nt][2] * inv1, o[nt][3] * inv1);
        *(__half2*)(Oh + r0 * (NH * HD) + c) = v0;
        *(__half2*)(Oh + (r0 + 8) * (NH * HD) + c) = v1;
    }
}

// ---------------- launch ----------------
extern "C" void kernel_launch(void* const* d_in, const int* in_sizes, int n_in,
                              void* d_out, int out_size) {
    const float* hs   = (const float*)d_in[0];
    const float* cosp = (const float*)d_in[2];
    const float* sinp = (const float*)d_in[3];
    const float* wq   = (const float*)d_in[4];
    const float* wk   = (const float*)d_in[5];
    const float* wv   = (const float*)d_in[6];
    const float* wo   = (const float*)d_in[7];
    float* out = (float*)d_out;

    float* qkv;
    __half *ath, *hsh, *wqh, *wkh, *wvh, *woh, *qs, *ks, *vt;
    cudaGetSymbolAddress((void**)&qkv, g_qkv);
    cudaGetSymbolAddress((void**)&ath, g_att_h);
    cudaGetSymbolAddress((void**)&hsh, g_hs_h);
    cudaGetSymbolAddress((void**)&wqh, g_wq_h);
    cudaGetSymbolAddress((void**)&wkh, g_wk_h);
    cudaGetSymbolAddress((void**)&wvh, g_wv_h);
    cudaGetSymbolAddress((void**)&woh, g_wo_h);
    cudaGetSymbolAddress((void**)&qs, g_q_s);
    cudaGetSymbolAddress((void**)&ks, g_k_s);
    cudaGetSymbolAddress((void**)&vt, g_vt);

    cudaFuncSetAttribute(gemm_tc,
                         cudaFuncAttributeMaxDynamicSharedMemorySize, GEMM_SMEM);
    cudaFuncSetAttribute(flash_tc,
                         cudaFuncAttributeMaxDynamicSharedMemorySize, FLASH_SMEM);

    const int RT = 256;
    const int n8_hs = S * HID / 8;
    const int n8_wq = NH * HD * HID / 8;
    const int n8_wk = NKV * HD * HID / 8;
    const float scale = 0.08838834764831845f;

    round_fp16_kernel<<<(n8_hs + RT - 1) / RT, RT>>>(hs, hsh, n8_hs);
    round_fp16_kernel<<<(n8_wq + RT - 1) / RT, RT>>>(wq, wqh, n8_wq);
    round2_fp16_kernel<<<(2 * n8_wk + RT - 1) / RT, RT>>>(wk, wkh, n8_wk, wv, wvh, n8_wk);
    // fused QKV projection — ncu capture slot
    gemm_tc<<<dim3(QKVN / BN, S / BM), 256, GEMM_SMEM>>>(
        hsh, wqh, wkh, wvh, NH * HD, NH * HD + NKV * HD, qkv, S, QKVN, HID);
    round_fp16_kernel<<<(n8_wq + RT - 1) / RT, RT>>>(wo, woh, n8_wq);
    rope_split_kernel<<<S * NH / 8, 256>>>(qkv, cosp, sinp, qs, NH, scale);
    rope_split_kernel<<<S * NKV / 8, 256>>>(qkv + 4096, cosp, sinp, ks, NKV, 1.0f);
    convert_v_kernel<<<dim3(S / 64, NKV), 256>>>(qkv, vt);
    flash_tc<<<dim3(S / FQ, NH), 256, FLASH_SMEM>>>(qs, ks, vt, ath);
    gemm_tc<<<dim3(HID / BN, S / BM), 256, GEMM_SMEM>>>(
        ath, woh, woh, woh, HID, HID, out, S, HID, HID);
}

// round 15
// speedup vs baseline: 1.1451x; 1.1451x over previous
#include <cuda_runtime.h>
#include <cuda_fp16.h>
#include <cstdint>

#define S 2048
#define HID 4096
#define NH 32
#define NKV 8
#define HD 128
#define QKVN 6144            // 4096 (q) + 1024 (k) + 1024 (v)

// ---------------- scratch (no allocation allowed) ----------------
__device__ float  g_qkv[(size_t)S * QKVN];
__device__ __half g_att_h[(size_t)S * NH * HD];
__device__ __half g_hs_h[(size_t)S * HID];
__device__ __half g_wq_h[(size_t)NH * HD * HID];
__device__ __half g_wk_h[(size_t)NKV * HD * HID];
__device__ __half g_wv_h[(size_t)NKV * HD * HID];
__device__ __half g_wo_h[(size_t)HID * NH * HD];
// flash pre-split hi/lo planes (k16-interleaved, flash-private layout)
__device__ __half g_q_s[(size_t)S * NH * 256];     // [s][h][2][128]
__device__ __half g_k_s[(size_t)S * NKV * 256];    // [s][kvh][2][128]
__device__ __half g_vt[(size_t)NKV * 2 * HD * S];  // [kvh][2][d][s-interleaved]

// ---------------- helpers ----------------
__device__ __forceinline__ void mma16816(float* d, uint32_t a0, uint32_t a1,
                                         uint32_t a2, uint32_t a3,
                                         uint32_t b0, uint32_t b1) {
    asm volatile(
        "mma.sync.aligned.m16n8k16.row.col.f32.f16.f16.f32 "
        "{%0,%1,%2,%3}, {%4,%5,%6,%7}, {%8,%9}, {%0,%1,%2,%3};"
        : "+f"(d[0]), "+f"(d[1]), "+f"(d[2]), "+f"(d[3])
        : "r"(a0), "r"(a1), "r"(a2), "r"(a3), "r"(b0), "r"(b1));
}

__device__ __forceinline__ void ldsm_x4(uint32_t& r0, uint32_t& r1,
                                        uint32_t& r2, uint32_t& r3, uint32_t addr) {
    asm volatile("ldmatrix.sync.aligned.m8n8.x4.shared.b16 {%0,%1,%2,%3}, [%4];"
                 : "=r"(r0), "=r"(r1), "=r"(r2), "=r"(r3) : "r"(addr));
}

__device__ __forceinline__ void split2(float x, float y, uint32_t& hi, uint32_t& lo) {
    __half2 h = __floats2half2_rn(x, y);
    float2 r = __half22float2(h);
    __half2 l = __floats2half2_rn(x - r.x, y - r.y);
    hi = *(uint32_t*)&h;
    lo = *(uint32_t*)&l;
}

__device__ __forceinline__ uint32_t smem_u32(const void* p) {
    uint32_t a;
    asm("{ .reg .u64 t; cvta.to.shared.u64 t, %1; cvt.u32.u64 %0, t; }" : "=r"(a) : "l"(p));
    return a;
}

__device__ __forceinline__ void cp_async16(uint32_t saddr, const void* gaddr) {
    asm volatile("cp.async.cg.shared.global [%0], [%1], 16;"
                 :: "r"(saddr), "l"(gaddr) : "memory");
}
#define CP_COMMIT() asm volatile("cp.async.commit_group;" ::: "memory")
#define CP_WAIT1()  asm volatile("cp.async.wait_group 1;" ::: "memory")
#define CP_WAIT0()  asm volatile("cp.async.wait_group 0;" ::: "memory")

__device__ __forceinline__ void lds64(uint32_t& x, uint32_t& y, uint32_t addr) {
    asm volatile("ld.shared.v2.b32 {%0,%1}, [%2];" : "=r"(x), "=r"(y) : "r"(addr));
}

// ---------------- plain fp16 conversion ----------------
__global__ void round_fp16_kernel(const float* __restrict__ in,
                                  __half* __restrict__ out, int n8) {
    int i = blockIdx.x * blockDim.x + threadIdx.x;
    if (i >= n8) return;
    float4 a = ((const float4*)in)[2 * i];
    float4 b = ((const float4*)in)[2 * i + 1];
    __half2 h0 = __floats2half2_rn(a.x, a.y);
    __half2 h1 = __floats2half2_rn(a.z, a.w);
    __half2 h2 = __floats2half2_rn(b.x, b.y);
    __half2 h3 = __floats2half2_rn(b.z, b.w);
    uint4 o;
    o.x = *(uint32_t*)&h0; o.y = *(uint32_t*)&h1;
    o.z = *(uint32_t*)&h2; o.w = *(uint32_t*)&h3;
    ((uint4*)out)[i] = o;
}

__global__ void round2_fp16_kernel(const float* __restrict__ inA, __half* __restrict__ outA, int n8A,
                                   const float* __restrict__ inB, __half* __restrict__ outB, int n8B) {
    int i = blockIdx.x * blockDim.x + threadIdx.x;
    const float4* src;
    uint4* dst;
    int j;
    if (i < n8A) { src = (const float4*)inA; dst = (uint4*)outA; j = i; }
    else { j = i - n8A; if (j >= n8B) return; src = (const float4*)inB; dst = (uint4*)outB; }
    float4 a = src[2 * j], b = src[2 * j + 1];
    __half2 h0 = __floats2half2_rn(a.x, a.y);
    __half2 h1 = __floats2half2_rn(a.z, a.w);
    __half2 h2 = __floats2half2_rn(b.x, b.y);
    __half2 h3 = __floats2half2_rn(b.z, b.w);
    uint4 o;
    o.x = *(uint32_t*)&h0; o.y = *(uint32_t*)&h1;
    o.z = *(uint32_t*)&h2; o.w = *(uint32_t*)&h3;
    dst[j] = o;
}

// ==================================================================
// fp16 GEMM (R13 verbatim): CTA 128x128, BK=64, warp 64x32,
// ldmatrix frags, 2-stage cp.async, 2 CTAs/SM.
// ==================================================================
#define BM 128
#define BN 128
#define BK 64
#define ROWB 144
#define TILEB (BM * ROWB)                 // 18432
#define STAGEB (2 * TILEB)                // 36864
#define GEMM_SMEM (2 * STAGEB)            // 73728 B

__global__ __launch_bounds__(256, 2) void gemm_tc(
        const __half* __restrict__ A,
        const __half* __restrict__ B0, const __half* __restrict__ B1,
        const __half* __restrict__ B2, int nb0, int nb1,
        float* __restrict__ C, int M, int N, int K) {
    extern __shared__ __align__(16) char smem[];
    const uint32_t sb = smem_u32(smem);

    const int tid = threadIdx.x;
    const int wid = tid >> 5;
    const int lane = tid & 31;
    const int wm = wid & 1;
    const int wn = wid >> 1;
    const int lr = lane >> 2;
    const int lc = lane & 3;

    const size_t row0 = (size_t)blockIdx.y * BM;
    const int col0 = blockIdx.x * BN;

    const __half* B;
    int bo;
    if (col0 < nb0)      { B = B0; bo = col0; }
    else if (col0 < nb1) { B = B1; bo = col0 - nb0; }
    else                 { B = B2; bo = col0 - nb1; }

    const __half* gA[4];
    const __half* gB[4];
    uint32_t sOff[4];
#pragma unroll
    for (int i = 0; i < 4; i++) {
        int cid = tid + 256 * i;
        int r = cid >> 3, c = cid & 7;
        gA[i] = A + (row0 + r) * (size_t)K + c * 8;
        gB[i] = B + (size_t)(bo + r) * K + c * 8;
        sOff[i] = (uint32_t)(r * ROWB + c * 16);
    }

    uint32_t relA[4];
#pragma unroll
    for (int mt = 0; mt < 4; mt++)
        relA[mt] = (uint32_t)((wm * 64 + mt * 16 + (lane & 15)) * ROWB + (lane >> 4) * 16);
    uint32_t relB[2];
#pragma unroll
    for (int p = 0; p < 2; p++)
        relB[p] = (uint32_t)((wn * 32 + (2 * p + (lane >> 4)) * 8 + (lane & 7)) * ROWB +
                             ((lane >> 3) & 1) * 16);

    float acc[4][4][4];
#pragma unroll
    for (int mt = 0; mt < 4; mt++)
#pragma unroll
        for (int nt = 0; nt < 4; nt++)
#pragma unroll
            for (int e = 0; e < 4; e++) acc[mt][nt][e] = 0.f;

    const int NKc = K / BK;

#pragma unroll
    for (int st = 0; st < 2; st++) {
        uint32_t base = sb + st * STAGEB;
#pragma unroll
        for (int i = 0; i < 4; i++) {
            cp_async16(base + sOff[i], gA[i] + st * BK);
            cp_async16(base + TILEB + sOff[i], gB[i] + st * BK);
        }
        CP_COMMIT();
    }

    for (int kc = 0; kc < NKc; kc++) {
        CP_WAIT1();
        __syncthreads();

        const uint32_t Abase = sb + (kc & 1) * STAGEB;
        const uint32_t Bbase = Abase + TILEB;

#pragma unroll
        for (int g = 0; g < 4; g++) {
            const uint32_t go = (uint32_t)(g * 32);
            uint32_t af[4][4], bf[4][2];
#pragma unroll
            for (int mt = 0; mt < 4; mt++)
                ldsm_x4(af[mt][0], af[mt][1], af[mt][2], af[mt][3],
                        Abase + relA[mt] + go);
#pragma unroll
            for (int p = 0; p < 2; p++)
                ldsm_x4(bf[2 * p][0], bf[2 * p][1], bf[2 * p + 1][0], bf[2 * p + 1][1],
                        Bbase + relB[p] + go);
#pragma unroll
            for (int mt = 0; mt < 4; mt++)
#pragma unroll
                for (int nt = 0; nt < 4; nt++)
                    mma16816(acc[mt][nt], af[mt][0], af[mt][1], af[mt][2], af[mt][3],
                             bf[nt][0], bf[nt][1]);
        }
        __syncthreads();

        if (kc + 2 < NKc) {
            uint32_t base = sb + (kc & 1) * STAGEB;
            const int koff = (kc + 2) * BK;
#pragma unroll
            for (int i = 0; i < 4; i++) {
                cp_async16(base + sOff[i], gA[i] + koff);
                cp_async16(base + TILEB + sOff[i], gB[i] + koff);
            }
        }
        CP_COMMIT();
    }

#pragma unroll
    for (int mt = 0; mt < 4; mt++) {
        size_t rg = row0 + wm * 64 + mt * 16 + lr;
#pragma unroll
        for (int nt = 0; nt < 4; nt++) {
            size_t cg = (size_t)col0 + wn * 32 + nt * 8 + lc * 2;
            *(float2*)(C + rg * N + cg) = make_float2(acc[mt][nt][0], acc[mt][nt][1]);
            *(float2*)(C + (rg + 8) * N + cg) = make_float2(acc[mt][nt][2], acc[mt][nt][3]);
        }
    }
}

// ==================================================================
// RoPE + fp16 hi/lo split (k16-interleaved, flash-private), warp per row.
// ==================================================================
__global__ void rope_split_kernel(const float* __restrict__ src,
                                  const float* __restrict__ cosp,
                                  const float* __restrict__ sinp,
                                  __half* __restrict__ dst,
                                  int nh, float scale) {
    int wpb = blockDim.x >> 5;
    int idx = blockIdx.x * wpb + (threadIdx.x >> 5);
    int lane = threadIdx.x & 31;
    int s = idx / nh, h = idx - s * nh;
    int d0 = 4 * lane;

    const float* row = src + (size_t)s * QKVN + h * HD;
    float4 x = *(const float4*)(row + d0);
    float4 c = *(const float4*)(cosp + s * HD + d0);
    float4 sn = *(const float4*)(sinp + s * HD + d0);
    float xs[4] = {x.x, x.y, x.z, x.w};
    float cs[4] = {c.x, c.y, c.z, c.w};
    float ss[4] = {sn.x, sn.y, sn.z, sn.w};
    float sign = (lane < 16) ? -1.f : 1.f;
    float out[4];
#pragma unroll
    for (int j = 0; j < 4; j++) {
        float p = __shfl_xor_sync(0xffffffffu, xs[j], 16);
        out[j] = (xs[j] * cs[j] + sign * p * ss[j]) * scale;
    }

    int g = lane >> 2;
    int e = 4 * (lane & 3);
    int s0 = (e < 8) ? e : e - 7;
    int s1 = (e + 2 < 8) ? e + 2 : e - 5;

    __half2 h0 = __floats2half2_rn(out[0], out[1]);
    __half2 h1 = __floats2half2_rn(out[2], out[3]);
    float2 r0 = __half22float2(h0), r1 = __half22float2(h1);
    __half2 l0 = __floats2half2_rn(out[0] - r0.x, out[1] - r0.y);
    __half2 l1 = __floats2half2_rn(out[2] - r1.x, out[3] - r1.y);

    __half2* dh = (__half2*)dst;
    size_t base = (size_t)(s * nh + h) * 128;
    dh[base + g * 8 + s0] = h0;
    dh[base + g * 8 + s1] = h1;
    dh[base + 64 + g * 8 + s0] = l0;
    dh[base + 64 + g * 8 + s1] = l1;
}

// ==================================================================
// V transpose + split (flash-private layout).
// ==================================================================
__global__ __launch_bounds__(256) void convert_v_kernel(const float* __restrict__ qkv,
                                                        __half* __restrict__ vt) {
    __shared__ float vsm[64][132];
    int s0 = blockIdx.x * 64;
    int kvh = blockIdx.y;
    int tid = threadIdx.x;

    for (int i = tid; i < 64 * 32; i += 256) {
        int r = i >> 5, c4 = (i & 31) * 4;
        float4 v = *(const float4*)(qkv + (size_t)(s0 + r) * QKVN + 5120 + kvh * HD + c4);
        vsm[r][c4] = v.x; vsm[r][c4 + 1] = v.y; vsm[r][c4 + 2] = v.z; vsm[r][c4 + 3] = v.w;
    }
    __syncthreads();

    int d = tid >> 1, hp = tid & 1;
    float v[32];
#pragma unroll
    for (int j = 0; j < 32; j++) v[j] = vsm[32 * hp + j][d];

#pragma unroll
    for (int g2 = 0; g2 < 2; g2++) {
        __half2 hi[8], lo[8];
#pragma unroll
        for (int slot = 0; slot < 8; slot++) {
            int e = (slot & 1) ? slot + 7 : slot;
            float x = v[g2 * 16 + e], y = v[g2 * 16 + e + 1];
            __half2 hh = __floats2half2_rn(x, y);
            float2 r = __half22float2(hh);
            hi[slot] = hh;
            lo[slot] = __floats2half2_rn(x - r.x, y - r.y);
        }
        int kbase = s0 + (2 * hp + g2) * 16;
        __half2* dhi = (__half2*)vt + ((((size_t)kvh * 2 + 0) * HD + d) * S + kbase) / 2;
        __half2* dlo = (__half2*)vt + ((((size_t)kvh * 2 + 1) * HD + d) * S + kbase) / 2;
#pragma unroll
        for (int slot = 0; slot < 8; slot++) { dhi[slot] = hi[slot]; dlo[slot] = lo[slot]; }
    }
}

// ==================================================================
// Flash attention v3 (FQ=64, 128 threads): separate K and V buffers,
// cross-iteration cp.async prefetch — K(kt+1) issued after QK^T(kt),
// V(kt) issued in prologue/previous iter. wait_group 1 discipline:
// commits ordered [..., V(kt), K(kt+1)] so wait1 at loop top covers
// K(kt); wait1 before PV covers V(kt). PV A-frags from score regs.
// SMEM: Q 2x17408 + K 2x18432 + V 2x20480 = 112640 B (2 CTAs/SM).
// ==================================================================
#define FQ 64
#define FK 64
#define QROWB 272
#define KROWB 288
#define VROWB 160
#define Q_PLANE (64 * QROWB)               // 17408
#define K_OFF (2 * Q_PLANE)                // 34816
#define K_PLANE (64 * KROWB)               // 18432
#define V_OFF (K_OFF + 2 * K_PLANE)        // 71680
#define V_PLANE (128 * VROWB)              // 20480
#define FLASH_SMEM (V_OFF + 2 * V_PLANE)   // 112640 B

__global__ __launch_bounds__(128) void flash_tc(const __half* __restrict__ Qsg,
                                                const __half* __restrict__ Ksg,
                                                const __half* __restrict__ VTg,
                                                __half* __restrict__ Oh) {
    extern __shared__ __align__(16) char fsm[];
    const uint32_t qhi_b = smem_u32(fsm);
    const uint32_t qlo_b = qhi_b + Q_PLANE;
    const uint32_t khi_b = qhi_b + K_OFF;
    const uint32_t klo_b = khi_b + K_PLANE;
    const uint32_t vhi_b = qhi_b + V_OFF;
    const uint32_t vlo_b = vhi_b + V_PLANE;

    const int h = blockIdx.y;
    const int kvh = h >> 2;
    const int qi = gridDim.x - 1 - blockIdx.x;
    const int q0 = qi * FQ;
    const int tid = threadIdx.x;
    const int wid = tid >> 5;
    const int lane = tid & 31;
    const int lr = lane >> 2;
    const int lc = lane & 3;
    const int nkt = qi + 1;

    // ---- prologue: Q, K(0), V(0) ----
#pragma unroll
    for (int ii = 0; ii < 16; ii++) {
        int i = tid + 128 * ii;
        int r = i >> 5, c = i & 31;
        int plane = c >> 4, j = c & 15;
        cp_async16((plane ? qlo_b : qhi_b) + (uint32_t)(r * QROWB + j * 16),
                   Qsg + ((size_t)(q0 + r) * NH + h) * 256 + plane * 128 + j * 8);
    }
    CP_COMMIT();
#pragma unroll
    for (int ii = 0; ii < 16; ii++) {
        int i = tid + 128 * ii;
        int r = i >> 5, c = i & 31;
        int plane = c >> 4, j = c & 15;
        cp_async16((plane ? klo_b : khi_b) + (uint32_t)(r * KROWB + j * 16),
                   Ksg + ((size_t)r * NKV + kvh) * 256 + plane * 128 + j * 8);
    }
    CP_COMMIT();
#pragma unroll
    for (int ii = 0; ii < 16; ii++) {
        int i = tid + 128 * ii;
        int plane = i >> 10;
        int rem = i & 1023;
        int d = rem >> 3, j = rem & 7;
        cp_async16((plane ? vlo_b : vhi_b) + (uint32_t)(d * VROWB + j * 16),
                   VTg + (((size_t)kvh * 2 + plane) * HD + d) * S + j * 8);
    }
    CP_COMMIT();

    float o[16][4];
#pragma unroll
    for (int nt = 0; nt < 16; nt++)
#pragma unroll
        for (int e = 0; e < 4; e++) o[nt][e] = 0.f;
    float m0 = -1e30f, m1 = -1e30f, l0v = 0.f, l1v = 0.f;

    for (int kt = 0; kt < nkt; kt++) {
        const int k0 = kt * FK;

        CP_WAIT1();        // everything except newest group (V(kt)) landed -> K(kt) ready
        __syncthreads();

        // ---- QK^T ----
        float sa[8][4];
#pragma unroll
        for (int nt = 0; nt < 8; nt++)
#pragma unroll
            for (int e = 0; e < 4; e++) sa[nt][e] = 0.f;

#pragma unroll 2
        for (int ks = 0; ks < 8; ks++) {
            const uint32_t go = (uint32_t)(ks * 32 + lc * 8);
            uint32_t ah[4], al[4];
            {
                uint32_t rq = (uint32_t)((wid * 16 + lr) * QROWB) + go;
                lds64(ah[0], ah[2], qhi_b + rq);
                lds64(ah[1], ah[3], qhi_b + rq + 8 * QROWB);
                lds64(al[0], al[2], qlo_b + rq);
                lds64(al[1], al[3], qlo_b + rq + 8 * QROWB);
            }
#pragma unroll
            for (int nt = 0; nt < 8; nt++) {
                uint32_t rk = (uint32_t)((nt * 8 + lr) * KROWB) + go;
                uint32_t bh0, bh1, bl0, bl1;
                lds64(bh0, bh1, khi_b + rk);
                lds64(bl0, bl1, klo_b + rk);
                mma16816(sa[nt], ah[0], ah[1], ah[2], ah[3], bh0, bh1);
                mma16816(sa[nt], ah[0], ah[1], ah[2], ah[3], bl0, bl1);
                mma16816(sa[nt], al[0], al[1], al[2], al[3], bh0, bh1);
            }
        }
        __syncthreads();   // all warps done reading K buffer

        // ---- prefetch K(kt+1) into the K buffer (overlaps softmax+PV) ----
        if (kt + 1 < nkt) {
            const int kn = k0 + FK;
#pragma unroll
            for (int ii = 0; ii < 16; ii++) {
                int i = tid + 128 * ii;
                int r = i >> 5, c = i & 31;
                int plane = c >> 4, j = c & 15;
                cp_async16((plane ? klo_b : khi_b) + (uint32_t)(r * KROWB + j * 16),
                           Ksg + ((size_t)(kn + r) * NKV + kvh) * 256 + plane * 128 + j * 8);
            }
        }
        CP_COMMIT();       // group: K(kt+1) (possibly empty)

        // ---- causal mask on diagonal tile ----
        if (kt == qi) {
            int r0 = q0 + wid * 16 + lr;
#pragma unroll
            for (int nt = 0; nt < 8; nt++) {
                int c = k0 + nt * 8 + lc * 2;
                if (c > r0)         sa[nt][0] = -1e30f;
                if (c + 1 > r0)     sa[nt][1] = -1e30f;
                if (c > r0 + 8)     sa[nt][2] = -1e30f;
                if (c + 1 > r0 + 8) sa[nt][3] = -1e30f;
            }
        }

        // ---- online softmax ----
        float rx0 = -1e30f, rx1 = -1e30f;
#pragma unroll
        for (int nt = 0; nt < 8; nt++) {
            rx0 = fmaxf(rx0, fmaxf(sa[nt][0], sa[nt][1]));
            rx1 = fmaxf(rx1, fmaxf(sa[nt][2], sa[nt][3]));
        }
        rx0 = fmaxf(rx0, __shfl_xor_sync(0xffffffffu, rx0, 1));
        rx0 = fmaxf(rx0, __shfl_xor_sync(0xffffffffu, rx0, 2));
        rx1 = fmaxf(rx1, __shfl_xor_sync(0xffffffffu, rx1, 1));
        rx1 = fmaxf(rx1, __shfl_xor_sync(0xffffffffu, rx1, 2));

        float mn0 = fmaxf(m0, rx0), mn1 = fmaxf(m1, rx1);
        float a0 = __expf(m0 - mn0), a1 = __expf(m1 - mn1);
        m0 = mn0; m1 = mn1;

        float rs0 = 0.f, rs1 = 0.f;
#pragma unroll
        for (int nt = 0; nt < 8; nt++) {
            sa[nt][0] = __expf(sa[nt][0] - mn0);
            sa[nt][1] = __expf(sa[nt][1] - mn0);
            sa[nt][2] = __expf(sa[nt][2] - mn1);
            sa[nt][3] = __expf(sa[nt][3] - mn1);
            rs0 += sa[nt][0] + sa[nt][1];
            rs1 += sa[nt][2] + sa[nt][3];
        }
        rs0 += __shfl_xor_sync(0xffffffffu, rs0, 1);
        rs0 += __shfl_xor_sync(0xffffffffu, rs0, 2);
        rs1 += __shfl_xor_sync(0xffffffffu, rs1, 1);
        rs1 += __shfl_xor_sync(0xffffffffu, rs1, 2);
        l0v = l0v * a0 + rs0;
        l1v = l1v * a1 + rs1;

#pragma unroll
        for (int nt = 0; nt < 16; nt++) {
            o[nt][0] *= a0; o[nt][1] *= a0;
            o[nt][2] *= a1; o[nt][3] *= a1;
        }

        CP_WAIT1();        // all except newest (K(kt+1)) -> V(kt) landed
        __syncthreads();

        // ---- PV: A-frags straight from sa registers ----
#pragma unroll
        for (int g = 0; g < 4; g++) {
            uint32_t ah[4], al[4];
            split2(sa[2 * g][0], sa[2 * g][1], ah[0], al[0]);
            split2(sa[2 * g][2], sa[2 * g][3], ah[1], al[1]);
            split2(sa[2 * g + 1][0], sa[2 * g + 1][1], ah[2], al[2]);
            split2(sa[2 * g + 1][2], sa[2 * g + 1][3], ah[3], al[3]);
            const uint32_t go = (uint32_t)(g * 32 + lc * 8);
#pragma unroll
            for (int nt = 0; nt < 16; nt++) {
                uint32_t rv = (uint32_t)((nt * 8 + lr) * VROWB) + go;
                uint32_t bh0, bh1, bl0, bl1;
                lds64(bh0, bh1, vhi_b + rv);
                lds64(bl0, bl1, vlo_b + rv);
                mma16816(o[nt], ah[0], ah[1], ah[2], ah[3], bh0, bh1);
                mma16816(o[nt], ah[0], ah[1], ah[2], ah[3], bl0, bl1);
                mma16816(o[nt], al[0], al[1], al[2], al[3], bh0, bh1);
            }
        }
        __syncthreads();   // all warps done reading V buffer

        // ---- prefetch V(kt+1) (overlaps next QK^T) ----
        if (kt + 1 < nkt) {
            const int kn = k0 + FK;
#pragma unroll
            for (int ii = 0; ii < 16; ii++) {
                int i = tid + 128 * ii;
                int plane = i >> 10;
                int rem = i & 1023;
                int d = rem >> 3, j = rem & 7;
                cp_async16((plane ? vlo_b : vhi_b) + (uint32_t)(d * VROWB + j * 16),
                           VTg + (((size_t)kvh * 2 + plane) * HD + d) * S + kn + j * 8);
            }
        }
        CP_COMMIT();       // group: V(kt+1) (possibly empty)
    }

    // epilogue: plain fp16 att rows
    float inv0 = 1.0f / l0v, inv1 = 1.0f / l1v;
    size_t r0 = q0 + wid * 16 + lr;
#pragma unroll
    for (int nt = 0; nt < 16; nt++) {
        size_t c = h * HD + nt * 8 + lc * 2;
        __half2 v0 = __floats2half2_rn(o[nt][0] * inv0, o[nt][1] * inv0);
        __half2 v1 = __floats2half2_rn(o[nt][2] * inv1, o[nt][3] * inv1);
        *(__half2*)(Oh + r0 * (NH * HD) + c) = v0;
        *(__half2*)(Oh + (r0 + 8) * (NH * HD) + c) = v1;
    }
}

// ---------------- launch ----------------
extern "C" void kernel_launch(void* const* d_in, const int* in_sizes, int n_in,
                              void* d_out, int out_size) {
    const float* hs   = (const float*)d_in[0];
    const float* cosp = (const float*)d_in[2];
    const float* sinp = (const float*)d_in[3];
    const float* wq   = (const float*)d_in[4];
    const float* wk   = (const float*)d_in[5];
    const float* wv   = (const float*)d_in[6];
    const float* wo   = (const float*)d_in[7];
    float* out = (float*)d_out;

    float* qkv;
    __half *ath, *hsh, *wqh, *wkh, *wvh, *woh, *qs, *ks, *vt;
    cudaGetSymbolAddress((void**)&qkv, g_qkv);
    cudaGetSymbolAddress((void**)&ath, g_att_h);
    cudaGetSymbolAddress((void**)&hsh, g_hs_h);
    cudaGetSymbolAddress((void**)&wqh, g_wq_h);
    cudaGetSymbolAddress((void**)&wkh, g_wk_h);
    cudaGetSymbolAddress((void**)&wvh, g_wv_h);
    cudaGetSymbolAddress((void**)&woh, g_wo_h);
    cudaGetSymbolAddress((void**)&qs, g_q_s);
    cudaGetSymbolAddress((void**)&ks, g_k_s);
    cudaGetSymbolAddress((void**)&vt, g_vt);

    cudaFuncSetAttribute(gemm_tc,
                         cudaFuncAttributeMaxDynamicSharedMemorySize, GEMM_SMEM);
    cudaFuncSetAttribute(flash_tc,
                         cudaFuncAttributeMaxDynamicSharedMemorySize, FLASH_SMEM);

    const int RT = 256;
    const int n8_hs = S * HID / 8;
    const int n8_wq = NH * HD * HID / 8;
    const int n8_wk = NKV * HD * HID / 8;
    const float scale = 0.08838834764831845f;

    round_fp16_kernel<<<(n8_hs + RT - 1) / RT, RT>>>(hs, hsh, n8_hs);
    round_fp16_kernel<<<(n8_wq + RT - 1) / RT, RT>>>(wq, wqh, n8_wq);
    round2_fp16_kernel<<<(2 * n8_wk + RT - 1) / RT, RT>>>(wk, wkh, n8_wk, wv, wvh, n8_wk);
    // fused QKV projection — ncu capture slot
    gemm_tc<<<dim3(QKVN / BN, S / BM), 256, GEMM_SMEM>>>(
        hsh, wqh, wkh, wvh, NH * HD, NH * HD + NKV * HD, qkv, S, QKVN, HID);
    round_fp16_kernel<<<(n8_wq + RT - 1) / RT, RT>>>(wo, woh, n8_wq);
    rope_split_kernel<<<S * NH / 8, 256>>>(qkv, cosp, sinp, qs, NH, scale);
    rope_split_kernel<<<S * NKV / 8, 256>>>(qkv + 4096, cosp, sinp, ks, NKV, 1.0f);
    convert_v_kernel<<<dim3(S / 64, NKV), 256>>>(qkv, vt);
    flash_tc<<<dim3(S / FQ, NH), 128, FLASH_SMEM>>>(qs, ks, vt, ath);
    gemm_tc<<<dim3(HID / BN, S / BM), 256, GEMM_SMEM>>>(
        ath, woh, woh, woh, HID, HID, out, S, HID, HID);
}